// round 17
// baseline (speedup 1.0000x reference)
#include <cuda_runtime.h>
#include <cuda_fp16.h>
#include <cstdint>

// VectorQuantizer: N=65536 rows, D=256, K=1024 codes.
// Pass 1 (hybrid): warps 0-3 run int8 dp4a on rows 0-31 (IDP pipe), warps 4-7
//   run HFMA2 half2 on rows 32-63 (FMA pipe) — both MAC pipes concurrently.
//   Flag margin: int8 rows < 3.0, fp16 rows < 0.5.
// vq_fix (batched two-tier): tier-1 fp32 shared e-stream; tier-2 (margin<1e-3)
//   compensated-fp32 exact + TIE_EPS=7.5e-5 window pick-lowest (R6-calibrated).

#define N_ROWS   65536
#define DIM      256
#define K_CODES  1024
#define BM       64
#define THR_I8   3.0f
#define THR_F16  0.5f
#define TIE_EPS  7.5e-5
#define AMB_CAP  65536
#define RB       8
#define XPAD     36            // x stage stride (32 rows + 4 pad)

#define QMAX   4.8f
#define QS     (127.0f / QMAX)
#define SINV   (QMAX / 127.0f)
#define SCALE2 (2.0f * SINV * SINV)

__device__ double   g_loss_acc;
__device__ float    g_enorm[K_CODES];
__device__ double   g_enorm_d[K_CODES];
__device__ float    g_eT[K_CODES * DIM];     // e transposed [k][d]
__device__ uint32_t g_eq[64 * K_CODES];      // int8 packed [d4][k]
__device__ __half2  g_e2[128 * K_CODES];     // half2 packed [d2][k]
__device__ int      g_idx[N_ROWS];
__device__ int      g_amb[AMB_CAP];
__device__ int      g_amb_count;

// smem word offsets
#define OFF_XSQ  0                      // 64 d4 x 36 = 2304
#define OFF_XS2  2304                   // 128 d2 x 36 = 4608
#define OFF_ESQ  6912                   // 64 d4 x 64 = 4096
#define OFF_ES2  11008                  // 128 d2 x 64 = 8192
#define OFF_SN   19200                  // 64
#define OFF_RV   19264                  // 1024
#define OFF_RS   20288                  // 1024
#define OFF_RI   21312                  // 1024
#define OFF_LRED 22336                  // 8
#define SMEM_FLOATS 22344
#define SMEM_BYTES  (SMEM_FLOATS * 4)   // 89376

__device__ __forceinline__ int q8(float v) {
    int q = __float2int_rn(v * QS);
    return max(-127, min(127, q));
}
__device__ __forceinline__ uint32_t pack4(float a, float b, float c, float d) {
    return (uint32_t)(q8(a) & 0xFF) | ((uint32_t)(q8(b) & 0xFF) << 8) |
           ((uint32_t)(q8(c) & 0xFF) << 16) | ((uint32_t)(q8(d) & 0xFF) << 24);
}

// ---------------------------------------------------------------------------
// prep: 0-255 transpose eT; 256-259 norms+reset; 260-323 pack eq; 324-451 pack e2.
__global__ void vq_prep(const float* __restrict__ e) {
    int b = blockIdx.x;
    if (b < 256) {
        int d = b;
        for (int k = threadIdx.x; k < K_CODES; k += 256)
            g_eT[k * DIM + d] = e[d * K_CODES + k];
    } else if (b < 260) {
        int k = (b - 256) * 256 + threadIdx.x;
        double s = 0.0;
        for (int d = 0; d < DIM; d++) {
            double v = (double)e[d * K_CODES + k];
            s += v * v;
        }
        g_enorm[k]   = (float)s;
        g_enorm_d[k] = s;
        if (b == 256 && threadIdx.x == 0) { g_loss_acc = 0.0; g_amb_count = 0; }
    } else if (b < 324) {
        int d4 = b - 260;
        for (int k = threadIdx.x; k < K_CODES; k += 256)
            g_eq[d4 * K_CODES + k] = pack4(
                e[(size_t)(4 * d4 + 0) * K_CODES + k],
                e[(size_t)(4 * d4 + 1) * K_CODES + k],
                e[(size_t)(4 * d4 + 2) * K_CODES + k],
                e[(size_t)(4 * d4 + 3) * K_CODES + k]);
    } else {
        int d2 = b - 324;
        for (int k = threadIdx.x; k < K_CODES; k += 256)
            g_e2[d2 * K_CODES + k] = __floats2half2_rn(
                e[(size_t)(2 * d2) * K_CODES + k],
                e[(size_t)(2 * d2 + 1) * K_CODES + k]);
    }
}

// ---------------------------------------------------------------------------
__global__ void __launch_bounds__(256) vq_main(const float* __restrict__ x,
                                               float* __restrict__ out) {
    extern __shared__ float sm[];
    uint32_t* xsq = (uint32_t*)(sm + OFF_XSQ);   // [d4][row 0..31]
    __half2*  xs2 = (__half2*)(sm + OFF_XS2);    // [d2][row 32..63 local]
    uint32_t* esq = (uint32_t*)(sm + OFF_ESQ);   // [d4][code]
    __half2*  es2 = (__half2*)(sm + OFF_ES2);    // [d2][code]
    float* snorm = sm + OFF_SN;
    float* rv = sm + OFF_RV;
    float* rs = sm + OFF_RS;
    int*   ri = (int*)(sm + OFF_RI);
    float* lred = sm + OFF_LRED;

    const int tid  = threadIdx.x;
    const int lane = tid & 31;
    const int wid  = tid >> 5;
    const int row0 = blockIdx.x * BM;
    const float* xblk = x + (size_t)row0 * DIM;

    // ---- stage x: rows 0-31 int8, rows 32-63 half2 ----
    #pragma unroll
    for (int it = 0; it < 8; it++) {            // 32 rows x 64 d4
        int i  = it * 256 + tid;
        int r  = i >> 6;                        // 0..31
        int d4 = i & 63;
        float4 v = ((const float4*)(xblk + (size_t)r * DIM))[d4];
        xsq[d4 * XPAD + r] = pack4(v.x, v.y, v.z, v.w);
    }
    #pragma unroll
    for (int it = 0; it < 8; it++) {            // rows 32-63 x 64 c4
        int i  = it * 256 + tid;
        int r  = i >> 6;                        // 0..31 (local)
        int c4 = i & 63;
        float4 v = ((const float4*)(xblk + (size_t)(r + 32) * DIM))[c4];
        int d2 = c4 * 2;
        xs2[d2 * XPAD + r]       = __floats2half2_rn(v.x, v.y);
        xs2[(d2 + 1) * XPAD + r] = __floats2half2_rn(v.z, v.w);
    }

    float bestv[4], secv[4];
    int   besti[4];
    #pragma unroll
    for (int i = 0; i < 4; i++) { bestv[i] = 3.4e38f; secv[i] = 3.4e38f; besti[i] = 0; }

    const bool isI8 = (wid < 4);
    const int wt  = isI8 ? tid : (tid - 128);
    const int tx  = wt & 15;
    const int ty  = wt >> 4;                    // 0..7
    const int tx4 = tx * 4;
    const int ty4 = ty * 4;

    for (int t = 0; t < 16; t++) {
        const int c0 = t * 64;

        __syncthreads();
        // stage esq (1024 uint4) + es2 (2048 uint4 worth = 8192 half2)
        #pragma unroll
        for (int q = 0; q < 4; q++) {
            int i  = tid * 4 + q;               // 0..1023
            int d4 = i >> 4, cq = (i & 15) * 4;
            *(uint4*)&esq[d4 * 64 + cq] =
                *(const uint4*)&g_eq[(size_t)d4 * K_CODES + c0 + cq];
        }
        #pragma unroll
        for (int q = 0; q < 8; q++) {
            int i  = tid * 8 + q;               // 0..2047
            int d2 = i >> 4, cq = (i & 15) * 4;
            *(uint4*)&es2[d2 * 64 + cq] =
                *(const uint4*)&g_e2[(size_t)d2 * K_CODES + c0 + cq];
        }
        if (tid < 64) snorm[tid] = g_enorm[c0 + tid];
        __syncthreads();

        if (isI8) {
            int acc[4][4];
            #pragma unroll
            for (int i = 0; i < 4; i++)
                #pragma unroll
                for (int j = 0; j < 4; j++) acc[i][j] = 0;
            #pragma unroll 8
            for (int d4 = 0; d4 < 64; d4++) {
                uint4 au = *(const uint4*)&xsq[d4 * XPAD + ty4];
                uint4 bu = *(const uint4*)&esq[d4 * 64 + tx4];
                int a0 = (int)au.x, a1 = (int)au.y, a2 = (int)au.z, a3 = (int)au.w;
                int b0 = (int)bu.x, b1 = (int)bu.y, b2 = (int)bu.z, b3 = (int)bu.w;
                acc[0][0] = __dp4a(a0, b0, acc[0][0]); acc[0][1] = __dp4a(a0, b1, acc[0][1]);
                acc[0][2] = __dp4a(a0, b2, acc[0][2]); acc[0][3] = __dp4a(a0, b3, acc[0][3]);
                acc[1][0] = __dp4a(a1, b0, acc[1][0]); acc[1][1] = __dp4a(a1, b1, acc[1][1]);
                acc[1][2] = __dp4a(a1, b2, acc[1][2]); acc[1][3] = __dp4a(a1, b3, acc[1][3]);
                acc[2][0] = __dp4a(a2, b0, acc[2][0]); acc[2][1] = __dp4a(a2, b1, acc[2][1]);
                acc[2][2] = __dp4a(a2, b2, acc[2][2]); acc[2][3] = __dp4a(a2, b3, acc[2][3]);
                acc[3][0] = __dp4a(a3, b0, acc[3][0]); acc[3][1] = __dp4a(a3, b1, acc[3][1]);
                acc[3][2] = __dp4a(a3, b2, acc[3][2]); acc[3][3] = __dp4a(a3, b3, acc[3][3]);
            }
            #pragma unroll
            for (int j = 0; j < 4; j++) {
                float n = snorm[tx4 + j];
                int  ci = c0 + tx4 + j;
                #pragma unroll
                for (int i = 0; i < 4; i++) {
                    float dist = fmaf(-SCALE2, (float)acc[i][j], n);
                    if (dist < bestv[i]) { secv[i] = bestv[i]; bestv[i] = dist; besti[i] = ci; }
                    else if (dist < secv[i]) secv[i] = dist;
                }
            }
        } else {
            float facc[4][4];
            #pragma unroll
            for (int i = 0; i < 4; i++)
                #pragma unroll
                for (int j = 0; j < 4; j++) facc[i][j] = 0.f;
            #pragma unroll
            for (int dk = 0; dk < 4; dk++) {
                __half2 acc2[4][4];
                #pragma unroll
                for (int i = 0; i < 4; i++)
                    #pragma unroll
                    for (int j = 0; j < 4; j++) acc2[i][j] = __floats2half2_rn(0.f, 0.f);
                const int db = dk * 32;
                #pragma unroll 8
                for (int d2 = 0; d2 < 32; d2++) {
                    uint4 au = *(const uint4*)&xs2[(db + d2) * XPAD + ty4];
                    uint4 bu = *(const uint4*)&es2[(db + d2) * 64 + tx4];
                    __half2 ax[4], bx[4];
                    *(uint4*)ax = au; *(uint4*)bx = bu;
                    #pragma unroll
                    for (int i = 0; i < 4; i++)
                        #pragma unroll
                        for (int j = 0; j < 4; j++)
                            acc2[i][j] = __hfma2(ax[i], bx[j], acc2[i][j]);
                }
                #pragma unroll
                for (int i = 0; i < 4; i++)
                    #pragma unroll
                    for (int j = 0; j < 4; j++)
                        facc[i][j] += __low2float(acc2[i][j]) + __high2float(acc2[i][j]);
            }
            #pragma unroll
            for (int j = 0; j < 4; j++) {
                float n = snorm[tx4 + j];
                int  ci = c0 + tx4 + j;
                #pragma unroll
                for (int i = 0; i < 4; i++) {
                    float dist = fmaf(-2.f, facc[i][j], n);
                    if (dist < bestv[i]) { secv[i] = bestv[i]; bestv[i] = dist; besti[i] = ci; }
                    else if (dist < secv[i]) secv[i] = dist;
                }
            }
        }
    }

    // ---- cross-tx reduce per row (int8 rows 0-31, fp16 rows 32-63) ----
    __syncthreads();
    const int rbase = isI8 ? ty4 : (32 + ty4);
    #pragma unroll
    for (int i = 0; i < 4; i++) {
        int row = rbase + i;
        rv[row * 16 + tx] = bestv[i];
        rs[row * 16 + tx] = secv[i];
        ri[row * 16 + tx] = besti[i];
    }
    __syncthreads();
    if (tid < BM) {
        int row = tid;
        float m1v = 3.4e38f, m2v = 3.4e38f;
        int m1i = 0;
        #pragma unroll
        for (int t = 0; t < 16; t++) {
            float v  = rv[row * 16 + t];
            int   i2 = ri[row * 16 + t];
            float s2 = rs[row * 16 + t];
            if (v < m1v) {
                if (m1v < m2v) m2v = m1v;
                m1v = v; m1i = i2;
            } else if (v < m2v) m2v = v;
            if (s2 < m2v) m2v = s2;
        }
        m1i &= (K_CODES - 1);
        int grow = row0 + row;
        g_idx[grow] = m1i;
        ri[row * 16] = m1i;
        float thr = (row < 32) ? THR_I8 : THR_F16;
        if (!(m2v - m1v >= thr)) {        // NaN-safe
            int slot = atomicAdd(&g_amb_count, 1);
            if (slot < AMB_CAP) g_amb[slot] = grow;
        }
    }
    __syncthreads();

    // ---- gather + straight-through output + loss (original fp32) ----
    float local = 0.f;
    #pragma unroll
    for (int rr = 0; rr < BM / 8; rr++) {
        int row = wid * 8 + rr;
        int idx = ri[row * 16] & (K_CODES - 1);
        const float* esrc = g_eT + (size_t)idx * DIM;
        const float* xrow = xblk + (size_t)row * DIM;
        float* orow = out + (size_t)(row0 + row) * DIM;
        #pragma unroll
        for (int kk = 0; kk < 8; kk++) {
            int d = kk * 32 + lane;
            float q  = esrc[d];
            float xv = xrow[d];
            float dq = q - xv;
            local += dq * dq;
            orow[d] = xv + dq;
        }
    }
    #pragma unroll
    for (int off = 16; off; off >>= 1)
        local += __shfl_xor_sync(0xffffffffu, local, off);
    if (lane == 0) lred[wid] = local;
    __syncthreads();
    if (tid == 0) {
        float ssum = 0.f;
        #pragma unroll
        for (int w = 0; w < 8; w++) ssum += lred[w];
        atomicAdd(&g_loss_acc, (double)ssum);
    }
}

// ---------------------------------------------------------------------------
// vq_fix batched two-tier (unchanged, proven).
__global__ void __launch_bounds__(256) vq_fix(const float* __restrict__ x,
                                              const float* __restrict__ e,
                                              float* __restrict__ out) {
    __shared__ float  xr[RB * DIM];
    __shared__ int    rows_s[RB];
    __shared__ float  frb[256], frs[256];
    __shared__ int    fri[256];
    __shared__ double sdd[256];
    __shared__ double svv[256];
    __shared__ int    sii[256];
    __shared__ double s_minv;

    const int tid = threadIdx.x;
    int total = g_amb_count; if (total > AMB_CAP) total = AMB_CAP;
    int ngroups = (total + RB - 1) / RB;

    for (int grp = blockIdx.x; grp < ngroups; grp += gridDim.x) {
        int base = grp * RB;
        int rcnt = total - base; if (rcnt > RB) rcnt = RB;

        if (tid < RB) rows_s[tid] = g_amb[base + (tid < rcnt ? tid : 0)];
        __syncthreads();
        for (int i = tid; i < RB * DIM; i += 256) {
            int r = i >> 8;
            xr[i] = (r < rcnt) ? x[(size_t)rows_s[r] * DIM + (i & 255)] : 0.f;
        }
        __syncthreads();

        float acc[RB][4];
        #pragma unroll
        for (int r = 0; r < RB; r++)
            #pragma unroll
            for (int j = 0; j < 4; j++) acc[r][j] = 0.f;

        const float* ebase = e + (size_t)tid * 4;
        #pragma unroll 4
        for (int d = 0; d < DIM; d++) {
            float4 ev = *(const float4*)(ebase + (size_t)d * K_CODES);
            #pragma unroll
            for (int r = 0; r < RB; r++) {
                float xv = xr[r * DIM + d];
                acc[r][0] = fmaf(xv, ev.x, acc[r][0]);
                acc[r][1] = fmaf(xv, ev.y, acc[r][1]);
                acc[r][2] = fmaf(xv, ev.z, acc[r][2]);
                acc[r][3] = fmaf(xv, ev.w, acc[r][3]);
            }
        }

        for (int r = 0; r < rcnt; r++) {
            int row = rows_s[r];
            float dj[4];
            #pragma unroll
            for (int j = 0; j < 4; j++)
                dj[j] = fmaf(-2.f, acc[r][j], g_enorm[tid * 4 + j]);

            float b = 3.4e38f, sv = 3.4e38f; int bi = 0;
            #pragma unroll
            for (int j = 0; j < 4; j++) {
                int k = tid * 4 + j;
                if (dj[j] < b) { sv = b; b = dj[j]; bi = k; }
                else if (dj[j] < sv) sv = dj[j];
            }
            frb[tid] = b; frs[tid] = sv; fri[tid] = bi;
            __syncthreads();
            for (int off = 128; off; off >>= 1) {
                if (tid < off) {
                    float b2 = frb[tid + off], s2v = frs[tid + off];
                    int   i2 = fri[tid + off];
                    float b1 = frb[tid], s1v = frs[tid];
                    int   i1 = fri[tid];
                    if (b2 < b1 || (b2 == b1 && i2 < i1)) {
                        frb[tid] = b2; fri[tid] = i2; frs[tid] = fminf(b1, s2v);
                    } else {
                        frs[tid] = fminf(s1v, b2);
                    }
                }
                __syncthreads();
            }
            float margin = frs[0] - frb[0];
            int newIdx = fri[0] & (K_CODES - 1);
            __syncthreads();

            if (!(margin >= 1e-3f)) {
                sdd[tid] = (double)xr[r * DIM + tid] * (double)xr[r * DIM + tid];
                __syncthreads();
                for (int off = 128; off; off >>= 1) {
                    if (tid < off) sdd[tid] += sdd[tid + off];
                    __syncthreads();
                }
                double xn = sdd[0];
                __syncthreads();

                float s[4] = {0.f, 0.f, 0.f, 0.f};
                float c[4] = {0.f, 0.f, 0.f, 0.f};
                #pragma unroll 4
                for (int d = 0; d < DIM; d++) {
                    float xv = xr[r * DIM + d];
                    float4 ev = *(const float4*)(ebase + (size_t)d * K_CODES);
                    float evs[4] = {ev.x, ev.y, ev.z, ev.w};
                    #pragma unroll
                    for (int j = 0; j < 4; j++) {
                        float p  = xv * evs[j];
                        float e1 = fmaf(xv, evs[j], -p);
                        float t  = s[j] + p;
                        float z  = t - s[j];
                        float e2 = (s[j] - (t - z)) + (p - z);
                        s[j] = t; c[j] += e1 + e2;
                    }
                }
                double dist[4];
                #pragma unroll
                for (int j = 0; j < 4; j++)
                    dist[j] = xn + g_enorm_d[tid * 4 + j]
                            - 2.0 * ((double)s[j] + (double)c[j]);

                double bv = 1e300; int bi2 = 0x7fffffff;
                #pragma unroll
                for (int j = 0; j < 4; j++) {
                    int k = tid * 4 + j;
                    if (dist[j] < bv || (dist[j] == bv && k < bi2)) { bv = dist[j]; bi2 = k; }
                }
                svv[tid] = bv; sii[tid] = bi2;
                __syncthreads();
                for (int off = 128; off; off >>= 1) {
                    if (tid < off) {
                        double v2 = svv[tid + off]; int i2 = sii[tid + off];
                        if (v2 < svv[tid] || (v2 == svv[tid] && i2 < sii[tid])) {
                            svv[tid] = v2; sii[tid] = i2;
                        }
                    }
                    __syncthreads();
                }
                if (tid == 0) s_minv = svv[0];
                __syncthreads();
                double minv = s_minv;

                int cand = 0x7fffffff;
                #pragma unroll
                for (int j = 0; j < 4; j++) {
                    int k = tid * 4 + j;
                    if (dist[j] <= minv + TIE_EPS && k < cand) cand = k;
                }
                sii[tid] = cand;
                __syncthreads();
                for (int off = 128; off; off >>= 1) {
                    if (tid < off) { if (sii[tid + off] < sii[tid]) sii[tid] = sii[tid + off]; }
                    __syncthreads();
                }
                newIdx = sii[0] & (K_CODES - 1);
                __syncthreads();
            }

            int oldIdx = g_idx[row];
            if (newIdx != oldIdx) {
                float xv = xr[r * DIM + tid];
                float qn = g_eT[(size_t)newIdx * DIM + tid];
                float qo = g_eT[(size_t)oldIdx * DIM + tid];
                out[(size_t)row * DIM + tid] = xv + (qn - xv);
                double dn = (double)(qn - xv), dl = (double)(qo - xv);
                sdd[tid] = dn * dn - dl * dl;
                __syncthreads();
                for (int off = 128; off; off >>= 1) {
                    if (tid < off) sdd[tid] += sdd[tid + off];
                    __syncthreads();
                }
                if (tid == 0) atomicAdd(&g_loss_acc, sdd[0]);
            }
            __syncthreads();
        }
    }
}

// ---------------------------------------------------------------------------
__global__ void vq_finish(float* __restrict__ out) {
    const double nd = (double)N_ROWS * (double)DIM;
    out[(size_t)N_ROWS * DIM] = (float)(1.25 * g_loss_acc / nd);
}

// ---------------------------------------------------------------------------
extern "C" void kernel_launch(void* const* d_in, const int* in_sizes, int n_in,
                              void* d_out, int out_size) {
    const float* x = (const float*)d_in[0];
    const float* e = (const float*)d_in[1];
    if (n_in >= 2 && in_sizes[0] == K_CODES * DIM && in_sizes[1] == N_ROWS * DIM) {
        e = (const float*)d_in[0];
        x = (const float*)d_in[1];
    }
    float* out = (float*)d_out;

    cudaFuncSetAttribute(vq_main, cudaFuncAttributeMaxDynamicSharedMemorySize, SMEM_BYTES);

    vq_prep<<<452, 256>>>(e);
    vq_main<<<N_ROWS / BM, 256, SMEM_BYTES>>>(x, out);
    vq_fix<<<2048, 256>>>(x, e, out);
    if (out_size > N_ROWS * DIM) vq_finish<<<1, 1>>>(out);
}